// round 12
// baseline (speedup 1.0000x reference)
#include <cuda_runtime.h>
#include <cuda_fp16.h>
#include <cstdint>
#include <math.h>

#define KT    64
#define VV    50000
#define DD    128
#define BOS_T 62
#define EOS_T 63
#define NB    8192
#define LL    126

#define EPS_F __uint_as_float(1u)
#define CORR_F   1363.2920638356958f   // 126 * log(50000)

// Scratch (no allocation allowed)
__device__ float g_T[VV * KT];                      // exp(logit) table (f32, [w][k])
__device__ __align__(128) __half g_Tb[VV * KT];     // permuted fp16 emissions
#define ZBLK 64
__device__ float g_ps[ZBLK * KT];                   // partial column sums

// ---------------------------------------------------------------------------
// helpers
// ---------------------------------------------------------------------------
__device__ __forceinline__ void fma2(unsigned long long& d,
                                     unsigned long long a,
                                     unsigned long long b) {
    asm("fma.rn.f32x2 %0, %1, %2, %0;" : "+l"(d) : "l"(a), "l"(b));
}
__device__ __forceinline__ float lo64(unsigned long long v) {
    return __uint_as_float((unsigned)(v & 0xffffffffull));
}
__device__ __forceinline__ float hi64(unsigned long long v) {
    return __uint_as_float((unsigned)(v >> 32));
}
__device__ __forceinline__ uint32_t pack_h2(float l, float h) {
    __half2 v = __floats2half2_rn(l, h);
    return *reinterpret_cast<uint32_t*>(&v);
}
__device__ __forceinline__ uint32_t hmul2u(uint32_t a, uint32_t b) {
    uint32_t r;
    asm("mul.rn.f16x2 %0, %1, %2;" : "=r"(r) : "r"(a), "r"(b));
    return r;
}
__device__ __forceinline__ uint32_t hmax2u(uint32_t a, uint32_t b) {
    uint32_t r;
    asm("max.f16x2 %0, %1, %2;" : "=r"(r) : "r"(a), "r"(b));
    return r;
}
__device__ __forceinline__ float h2lo(uint32_t u) {
    __half2 v = *reinterpret_cast<__half2*>(&u);
    return __low2float(v);
}
__device__ __forceinline__ float h2hi(uint32_t u) {
    __half2 v = *reinterpret_cast<__half2*>(&u);
    return __high2float(v);
}

// f16-accumulate MMA
__device__ __forceinline__ void mma16816h(uint32_t* c, const uint32_t* a,
                                          const uint32_t* b) {
    asm volatile(
        "mma.sync.aligned.m16n8k16.row.col.f16.f16.f16.f16 "
        "{%0,%1}, {%2,%3,%4,%5}, {%6,%7}, {%0,%1};"
        : "+r"(c[0]), "+r"(c[1])
        : "r"(a[0]), "r"(a[1]), "r"(a[2]), "r"(a[3]), "r"(b[0]), "r"(b[1]));
}
// f32-accumulate variant for the final EOS transition
__device__ __forceinline__ void mma16816f(float* c, const uint32_t* a,
                                          const uint32_t* b) {
    asm volatile(
        "mma.sync.aligned.m16n8k16.row.col.f32.f16.f16.f32 "
        "{%0,%1,%2,%3}, {%4,%5,%6,%7}, {%8,%9}, {%0,%1,%2,%3};"
        : "+f"(c[0]), "+f"(c[1]), "+f"(c[2]), "+f"(c[3])
        : "r"(a[0]), "r"(a[1]), "r"(a[2]), "r"(a[3]), "r"(b[0]), "r"(b[1]));
}

// ---------------------------------------------------------------------------
// Kernel 1: g_T[w*64+k] = exp(dot(ThetaB[k], E[w]))
// ---------------------------------------------------------------------------
#define WPB 16
#define TB_STRIDE 132

__global__ void __launch_bounds__(256) logits_kernel(const float* __restrict__ ThetaB,
                                                     const float* __restrict__ E) {
    __shared__ __align__(16) float Tbs[KT * TB_STRIDE];
    __shared__ __align__(16) float Es[WPB * DD];

    int tid = threadIdx.x;
    int wbase = blockIdx.x * WPB;

    for (int idx = tid; idx < KT * DD; idx += 256) {
        int k = idx >> 7, d = idx & 127;
        Tbs[k * TB_STRIDE + d] = ThetaB[idx];
    }
    for (int idx = tid; idx < WPB * DD; idx += 256)
        Es[idx] = E[(size_t)wbase * DD + idx];
    __syncthreads();

    int k  = tid & 63;
    int ws = tid >> 6;
    unsigned long long a0 = 0, a1 = 0, a2 = 0, a3 = 0;
    #pragma unroll 8
    for (int d = 0; d < DD; d += 4) {
        ulonglong2 tb = *reinterpret_cast<const ulonglong2*>(&Tbs[k * TB_STRIDE + d]);
        ulonglong2 e0 = *reinterpret_cast<const ulonglong2*>(&Es[(ws + 0) * DD + d]);
        ulonglong2 e1 = *reinterpret_cast<const ulonglong2*>(&Es[(ws + 4) * DD + d]);
        ulonglong2 e2 = *reinterpret_cast<const ulonglong2*>(&Es[(ws + 8) * DD + d]);
        ulonglong2 e3 = *reinterpret_cast<const ulonglong2*>(&Es[(ws + 12) * DD + d]);
        fma2(a0, tb.x, e0.x); fma2(a0, tb.y, e0.y);
        fma2(a1, tb.x, e1.x); fma2(a1, tb.y, e1.y);
        fma2(a2, tb.x, e2.x); fma2(a2, tb.y, e2.y);
        fma2(a3, tb.x, e3.x); fma2(a3, tb.y, e3.y);
    }
    g_T[(size_t)(wbase + ws + 0)  * KT + k] = __expf(lo64(a0) + hi64(a0));
    g_T[(size_t)(wbase + ws + 4)  * KT + k] = __expf(lo64(a1) + hi64(a1));
    g_T[(size_t)(wbase + ws + 8)  * KT + k] = __expf(lo64(a2) + hi64(a2));
    g_T[(size_t)(wbase + ws + 12) * KT + k] = __expf(lo64(a3) + hi64(a3));
}

// ---------------------------------------------------------------------------
// Kernel 2: partial column sums of exp table
// ---------------------------------------------------------------------------
__global__ void __launch_bounds__(256) zred1_kernel() {
    int r0 = (int)(((long long)blockIdx.x * VV) / ZBLK);
    int r1 = (int)(((long long)(blockIdx.x + 1) * VV) / ZBLK);
    int tid = threadIdx.x;
    int k = tid & 63, g = tid >> 6;
    float s = 0.f;
    for (int r = r0 + g; r < r1; r += 4)
        s += g_T[(size_t)r * KT + k];
    __shared__ float ss[256];
    ss[tid] = s;
    __syncthreads();
    if (g == 0) {
        s += ss[tid + 64] + ss[tid + 128] + ss[tid + 192];
        g_ps[blockIdx.x * KT + k] = s;
    }
}

// ---------------------------------------------------------------------------
// Kernel 3: bprob + fused final reduce -> permuted fp16 emission table.
// u32 slot (t*8+nc) = cols (8nc+2t, 8nc+2t+1). Cols 62,63 -> 0.
// ---------------------------------------------------------------------------
__global__ void __launch_bounds__(256) bprob_kernel() {
    __shared__ float Ss[KT];
    int tid = threadIdx.x;
    if (tid < KT) {
        float s = 0.f;
        #pragma unroll 8
        for (int b = 0; b < ZBLK; b++)
            s += g_ps[b * KT + tid];
        Ss[tid] = (float)VV / s;
    }
    __syncthreads();
    int idx = blockIdx.x * 256 + tid;
    if (idx >= VV * 4) return;
    int w = idx >> 2, t = idx & 3;
    const float2* row = reinterpret_cast<const float2*>(g_T + (size_t)w * KT);
    unsigned u[8];
    #pragma unroll
    for (int nc = 0; nc < 8; nc++) {
        float2 v = row[4 * nc + t];
        int c = 8 * nc + 2 * t;
        float a = v.x * Ss[c];
        float b = v.y * Ss[c + 1];
        if (t == 3 && nc == 7) { a = 0.f; b = 0.f; }   // BOS/EOS cols 62,63
        u[nc] = pack_h2(a, b);
    }
    uint4* dst = reinterpret_cast<uint4*>(g_Tb) + (size_t)w * 8 + t * 2;
    dst[0] = make_uint4(u[0], u[1], u[2], u[3]);
    dst[1] = make_uint4(u[4], u[5], u[6], u[7]);
}

// ---------------------------------------------------------------------------
// Kernel 4: fp16 mma.sync forward, n-split across 4 warps per block.
// Block = 128 threads = 4 warps = 16 sentences. Warp w owns cols 16w..16w+15
// (n-chunks 2w, 2w+1). Alpha exchanged per step via double-buffered permuted
// smem (row stride 36 u32). One __syncthreads per step. Rescale every 8 steps
// at rebuild time (warp-local, identical in all warps).
// ---------------------------------------------------------------------------
#define AROW 36   // u32 row stride in alpha buffers

__global__ void __launch_bounds__(128) forward_mma_kernel(const int* __restrict__ words,
                                                          const float* __restrict__ WA,
                                                          float* __restrict__ out) {
    __shared__ float As[KT * KT];                 // 16 KB transition probs
    __shared__ __align__(16) uint32_t alf[2][16 * AROW];   // 4.6 KB alpha exchange

    int tid  = threadIdx.x;
    int warp = tid >> 5;
    int lane = tid & 31;
    int g = lane >> 2;        // row group: rows g, g+8 (sentences)
    int t = lane & 3;         // quad col/k group

    // --- inline prep_A: thread k (<64) computes softmax row k of WA ---
    if (tid < KT) {
        int k = tid;
        float m = -INFINITY;
        for (int j = 0; j < KT; j++) {
            float v = WA[k * KT + j];
            if (j == BOS_T) v = -INFINITY;
            As[k * KT + j] = v;
            m = fmaxf(m, v);
        }
        float s = 0.f;
        for (int j = 0; j < KT; j++) {
            float e = (j == BOS_T) ? 0.f : __expf(As[k * KT + j] - m);
            As[k * KT + j] = e;
            s += e;
        }
        float inv = 1.0f / s;
        for (int j = 0; j < KT; j++)
            As[k * KT + j] = As[k * KT + j] * inv + EPS_F;
    }
    // zero alpha buffer 0 while warps wait
    for (int i = tid; i < 16 * AROW; i += 128) alf[0][i] = 0u;
    __syncthreads();

    // one-hot init: k pair {62,63} = slot [row][t=3][nc=7]
    if (tid < 16) alf[0][tid * AROW + 3 * 8 + 7] = 0x00003C00u;  // {1.0h, 0}

    int base = blockIdx.x * 16;

    // B fragments for this warp's two n-chunks
    uint32_t Bf[2][4][2];
    #pragma unroll
    for (int i = 0; i < 2; i++) {
        int n = 8 * (2 * warp + i) + g;
        #pragma unroll
        for (int kc = 0; kc < 4; kc++) {
            int k0 = 16 * kc + 2 * t;
            Bf[i][kc][0] = pack_h2(As[(k0 + 0) * KT + n], As[(k0 + 1) * KT + n]);
            Bf[i][kc][1] = pack_h2(As[(k0 + 8) * KT + n], As[(k0 + 9) * KT + n]);
        }
    }

    const int* wpg = words + (size_t)(base + g) * LL;
    const int* wph = words + (size_t)(base + g + 8) * LL;
    const uint2* Tb2 = reinterpret_cast<const uint2*>(g_Tb);   // 16 uint2 per word

    // emission for step 0 (this warp's 2 n-chunks, rows g and g+8)
    uint2 eg = Tb2[(size_t)wpg[0] * 16 + t * 4 + warp];
    uint2 eh = Tb2[(size_t)wph[0] * 16 + t * 4 + warp];
    int wg1 = wpg[1], wh1 = wph[1];

    float lsc0 = 0.f, lsc1 = 0.f;
    int cur = 0;

    __syncthreads();   // one-hot + Bf(As) visible

    uint32_t af[4][4];

    for (int step = 0; step < LL; step++) {
        // rebuild full alpha fragment from smem (all warps identical)
        {
            const uint32_t* src = alf[cur];
            uint4 q0 = *reinterpret_cast<const uint4*>(&src[g * AROW + t * 8 + 0]);
            uint4 q1 = *reinterpret_cast<const uint4*>(&src[g * AROW + t * 8 + 4]);
            uint4 r0 = *reinterpret_cast<const uint4*>(&src[(g + 8) * AROW + t * 8 + 0]);
            uint4 r1 = *reinterpret_cast<const uint4*>(&src[(g + 8) * AROW + t * 8 + 4]);
            af[0][0] = q0.x; af[0][2] = q0.y; af[1][0] = q0.z; af[1][2] = q0.w;
            af[2][0] = q1.x; af[2][2] = q1.y; af[3][0] = q1.z; af[3][2] = q1.w;
            af[0][1] = r0.x; af[0][3] = r0.y; af[1][1] = r0.z; af[1][3] = r0.w;
            af[2][1] = r1.x; af[2][3] = r1.y; af[3][1] = r1.z; af[3][3] = r1.w;
        }

        if ((step & 7) == 0 && step) {
            // rescale (identical in every warp): row maxes via f16x2 + quad shfl
            uint32_t m2g = af[0][0], m2h = af[0][1];
            #pragma unroll
            for (int kc = 0; kc < 4; kc++) {
                m2g = hmax2u(m2g, hmax2u(af[kc][0], af[kc][2]));
                m2h = hmax2u(m2h, hmax2u(af[kc][1], af[kc][3]));
            }
            float m0 = fmaxf(h2lo(m2g), h2hi(m2g));
            float m1 = fmaxf(h2lo(m2h), h2hi(m2h));
            m0 = fmaxf(m0, __shfl_xor_sync(0xffffffffu, m0, 1));
            m0 = fmaxf(m0, __shfl_xor_sync(0xffffffffu, m0, 2));
            m1 = fmaxf(m1, __shfl_xor_sync(0xffffffffu, m1, 1));
            m1 = fmaxf(m1, __shfl_xor_sync(0xffffffffu, m1, 2));
            float r0 = __fdividef(1.0f, m0);
            float r1 = __fdividef(1.0f, m1);
            lsc0 += __logf(m0);
            lsc1 += __logf(m1);
            uint32_t hr0 = pack_h2(r0, r0);
            uint32_t hr1 = pack_h2(r1, r1);
            #pragma unroll
            for (int kc = 0; kc < 4; kc++) {
                af[kc][0] = hmul2u(af[kc][0], hr0);
                af[kc][2] = hmul2u(af[kc][2], hr0);
                af[kc][1] = hmul2u(af[kc][1], hr1);
                af[kc][3] = hmul2u(af[kc][3], hr1);
            }
        }

        // D = alpha @ A_hmm for this warp's 2 n-chunks (f16 accum)
        uint32_t c0[2] = {0u, 0u}, c1[2] = {0u, 0u};
        #pragma unroll
        for (int kc = 0; kc < 4; kc++) mma16816h(c0, af[kc], Bf[0][kc]);
        #pragma unroll
        for (int kc = 0; kc < 4; kc++) mma16816h(c1, af[kc], Bf[1][kc]);

        // emission multiply -> store to other buffer (slots [row][t][2w,2w+1])
        {
            uint32_t* dst = alf[cur ^ 1];
            unsigned long long pg =
                (unsigned long long)hmul2u(c0[0], eg.x) |
                ((unsigned long long)hmul2u(c1[0], eg.y) << 32);
            unsigned long long ph =
                (unsigned long long)hmul2u(c0[1], eh.x) |
                ((unsigned long long)hmul2u(c1[1], eh.y) << 32);
            *reinterpret_cast<unsigned long long*>(&dst[g * AROW + t * 8 + 2 * warp]) = pg;
            *reinterpret_cast<unsigned long long*>(&dst[(g + 8) * AROW + t * 8 + 2 * warp]) = ph;
        }

        // prefetch next emissions + word after
        eg = Tb2[(size_t)wg1 * 16 + t * 4 + warp];
        eh = Tb2[(size_t)wh1 * 16 + t * 4 + warp];
        int nx = (step + 2 < LL) ? step + 2 : LL - 1;
        wg1 = wpg[nx]; wh1 = wph[nx];

        __syncthreads();
        cur ^= 1;
    }

    // final rebuild + EOS transition (f32 accum). Col 63 lives in nc=7 -> warp 3.
    if (warp == 3) {
        const uint32_t* src = alf[cur];
        uint4 q0 = *reinterpret_cast<const uint4*>(&src[g * AROW + t * 8 + 0]);
        uint4 q1 = *reinterpret_cast<const uint4*>(&src[g * AROW + t * 8 + 4]);
        uint4 r0 = *reinterpret_cast<const uint4*>(&src[(g + 8) * AROW + t * 8 + 0]);
        uint4 r1 = *reinterpret_cast<const uint4*>(&src[(g + 8) * AROW + t * 8 + 4]);
        af[0][0] = q0.x; af[0][2] = q0.y; af[1][0] = q0.z; af[1][2] = q0.w;
        af[2][0] = q1.x; af[2][2] = q1.y; af[3][0] = q1.z; af[3][2] = q1.w;
        af[0][1] = r0.x; af[0][3] = r0.y; af[1][1] = r0.z; af[1][3] = r0.w;
        af[2][1] = r1.x; af[2][3] = r1.y; af[3][1] = r1.z; af[3][3] = r1.w;

        float cz[4] = {0.f, 0.f, 0.f, 0.f};
        #pragma unroll
        for (int kc = 0; kc < 4; kc++)
            mma16816f(cz, af[kc], Bf[1][kc]);   // nc=7

        if (t == 3) {
            out[base + g]     = lsc0 + __logf(cz[1]) - CORR_F;
            out[base + g + 8] = lsc1 + __logf(cz[3]) - CORR_F;
        }
    }
}

// ---------------------------------------------------------------------------
// Launch (4 kernels)
// ---------------------------------------------------------------------------
extern "C" void kernel_launch(void* const* d_in, const int* in_sizes, int n_in,
                              void* d_out, int out_size) {
    const int*   words  = nullptr;
    const float* ThetaB = nullptr;
    const float* WA     = nullptr;
    const float* E      = nullptr;
    for (int i = 0; i < n_in; i++) {
        switch (in_sizes[i]) {
            case NB * LL:  words  = (const int*)d_in[i];   break;
            case KT * DD:  ThetaB = (const float*)d_in[i]; break;
            case KT * KT:  WA     = (const float*)d_in[i]; break;
            case VV * DD:  E      = (const float*)d_in[i]; break;
            default: break;
        }
    }
    float* out = (float*)d_out;

    logits_kernel<<<VV / WPB, 256>>>(ThetaB, E);
    zred1_kernel<<<ZBLK, 256>>>();
    bprob_kernel<<<(VV * 4 + 255) / 256, 256>>>();
    forward_mma_kernel<<<NB / 16, 128>>>(words, WA, out);
}

// round 14
// speedup vs baseline: 1.4598x; 1.4598x over previous
#include <cuda_runtime.h>
#include <cuda_bf16.h>
#include <cstdint>
#include <math.h>

#define KT    64
#define VV    50000
#define DD    128
#define BOS_T 62
#define EOS_T 63
#define NB    8192
#define LL    126

#define EPS_F __uint_as_float(1u)
#define CORR_F   1363.2920638356958f   // 126 * log(50000)

// Scratch (no allocation allowed)
__device__ float g_A[KT * KT];                       // transition probs, f32 [k][j]
__device__ float g_T[VV * KT];                       // exp(logit) table (f32)
__device__ __align__(128) __nv_bfloat16 g_Tb[VV * KT];  // permuted bf16 emissions
#define ZBLK 64
__device__ float g_ps[ZBLK * KT];                    // partial column sums

// ---------------------------------------------------------------------------
// helpers
// ---------------------------------------------------------------------------
__device__ __forceinline__ void fma2(unsigned long long& d,
                                     unsigned long long a,
                                     unsigned long long b) {
    asm("fma.rn.f32x2 %0, %1, %2, %0;" : "+l"(d) : "l"(a), "l"(b));
}
__device__ __forceinline__ float lo64(unsigned long long v) {
    return __uint_as_float((unsigned)(v & 0xffffffffull));
}
__device__ __forceinline__ float hi64(unsigned long long v) {
    return __uint_as_float((unsigned)(v >> 32));
}
__device__ __forceinline__ uint32_t pack_bf2(float l, float h) {
    uint32_t r;
    asm("cvt.rn.bf16x2.f32 %0, %1, %2;" : "=r"(r) : "f"(h), "f"(l));
    return r;
}
__device__ __forceinline__ uint32_t mulbf2(uint32_t a, uint32_t b) {
    uint32_t r;
    asm("mul.bf16x2 %0, %1, %2;" : "=r"(r) : "r"(a), "r"(b));
    return r;
}
__device__ __forceinline__ float blo(uint32_t e) {
    return __uint_as_float(e << 16);
}
__device__ __forceinline__ float bhi(uint32_t e) {
    return __uint_as_float(e & 0xffff0000u);
}

// D[m16,n8] += A[m16,k16] * B[k16,n8], bf16 in, f32 accum
__device__ __forceinline__ void mma16816(float* c, const uint32_t* a,
                                         const uint32_t* b) {
    asm volatile(
        "mma.sync.aligned.m16n8k16.row.col.f32.bf16.bf16.f32 "
        "{%0,%1,%2,%3}, {%4,%5,%6,%7}, {%8,%9}, {%0,%1,%2,%3};"
        : "+f"(c[0]), "+f"(c[1]), "+f"(c[2]), "+f"(c[3])
        : "r"(a[0]), "r"(a[1]), "r"(a[2]), "r"(a[3]), "r"(b[0]), "r"(b[1]));
}

// ---------------------------------------------------------------------------
// Kernel 1: A = softmax(WA, BOS col -> -inf) + EPS, f32 row-major
// ---------------------------------------------------------------------------
__global__ void prep_A_kernel(const float* __restrict__ WA) {
    int k = threadIdx.x;
    if (k >= KT) return;
    float x[KT];
    float m = -INFINITY;
    #pragma unroll
    for (int j = 0; j < KT; j++) {
        float v = WA[k * KT + j];
        if (j == BOS_T) v = -INFINITY;
        x[j] = v;
        m = fmaxf(m, v);
    }
    float s = 0.f;
    #pragma unroll
    for (int j = 0; j < KT; j++) {
        float e = (j == BOS_T) ? 0.f : __expf(x[j] - m);
        x[j] = e;
        s += e;
    }
    float inv = 1.0f / s;
    #pragma unroll
    for (int j = 0; j < KT; j++)
        g_A[k * KT + j] = x[j] * inv + EPS_F;
}

// ---------------------------------------------------------------------------
// Kernel 2: g_T[w*64+k] = exp(dot(ThetaB[k], E[w]))
// ---------------------------------------------------------------------------
#define WPB 16
#define TB_STRIDE 132

__global__ void __launch_bounds__(256) logits_kernel(const float* __restrict__ ThetaB,
                                                     const float* __restrict__ E) {
    __shared__ __align__(16) float Tbs[KT * TB_STRIDE];
    __shared__ __align__(16) float Es[WPB * DD];

    int tid = threadIdx.x;
    int wbase = blockIdx.x * WPB;

    for (int idx = tid; idx < KT * DD; idx += 256) {
        int k = idx >> 7, d = idx & 127;
        Tbs[k * TB_STRIDE + d] = ThetaB[idx];
    }
    for (int idx = tid; idx < WPB * DD; idx += 256)
        Es[idx] = E[(size_t)wbase * DD + idx];
    __syncthreads();

    int k  = tid & 63;
    int ws = tid >> 6;
    unsigned long long a0 = 0, a1 = 0, a2 = 0, a3 = 0;
    #pragma unroll 8
    for (int d = 0; d < DD; d += 4) {
        ulonglong2 tb = *reinterpret_cast<const ulonglong2*>(&Tbs[k * TB_STRIDE + d]);
        ulonglong2 e0 = *reinterpret_cast<const ulonglong2*>(&Es[(ws + 0) * DD + d]);
        ulonglong2 e1 = *reinterpret_cast<const ulonglong2*>(&Es[(ws + 4) * DD + d]);
        ulonglong2 e2 = *reinterpret_cast<const ulonglong2*>(&Es[(ws + 8) * DD + d]);
        ulonglong2 e3 = *reinterpret_cast<const ulonglong2*>(&Es[(ws + 12) * DD + d]);
        fma2(a0, tb.x, e0.x); fma2(a0, tb.y, e0.y);
        fma2(a1, tb.x, e1.x); fma2(a1, tb.y, e1.y);
        fma2(a2, tb.x, e2.x); fma2(a2, tb.y, e2.y);
        fma2(a3, tb.x, e3.x); fma2(a3, tb.y, e3.y);
    }
    g_T[(size_t)(wbase + ws + 0)  * KT + k] = __expf(lo64(a0) + hi64(a0));
    g_T[(size_t)(wbase + ws + 4)  * KT + k] = __expf(lo64(a1) + hi64(a1));
    g_T[(size_t)(wbase + ws + 8)  * KT + k] = __expf(lo64(a2) + hi64(a2));
    g_T[(size_t)(wbase + ws + 12) * KT + k] = __expf(lo64(a3) + hi64(a3));
}

// ---------------------------------------------------------------------------
// Kernel 3: partial column sums of exp table
// ---------------------------------------------------------------------------
__global__ void __launch_bounds__(256) zred1_kernel() {
    int r0 = (int)(((long long)blockIdx.x * VV) / ZBLK);
    int r1 = (int)(((long long)(blockIdx.x + 1) * VV) / ZBLK);
    int tid = threadIdx.x;
    int k = tid & 63, g = tid >> 6;
    float s = 0.f;
    for (int r = r0 + g; r < r1; r += 4)
        s += g_T[(size_t)r * KT + k];
    __shared__ float ss[256];
    ss[tid] = s;
    __syncthreads();
    if (g == 0) {
        s += ss[tid + 64] + ss[tid + 128] + ss[tid + 192];
        g_ps[blockIdx.x * KT + k] = s;
    }
}

// ---------------------------------------------------------------------------
// Kernel 4: bprob + fused final reduce -> permuted bf16 emission table.
// u32 slot (t*8+nc) = cols (8nc+2t, 8nc+2t+1). Cols 62,63 -> 0.
// ---------------------------------------------------------------------------
__global__ void __launch_bounds__(256) bprob_kernel() {
    __shared__ float Ss[KT];
    int tid = threadIdx.x;
    if (tid < KT) {
        float s = 0.f;
        #pragma unroll 8
        for (int b = 0; b < ZBLK; b++)
            s += g_ps[b * KT + tid];
        Ss[tid] = (float)VV / s;
    }
    __syncthreads();
    int idx = blockIdx.x * 256 + tid;
    if (idx >= VV * 4) return;
    int w = idx >> 2, t = idx & 3;
    const float2* row = reinterpret_cast<const float2*>(g_T + (size_t)w * KT);
    unsigned u[8];
    #pragma unroll
    for (int nc = 0; nc < 8; nc++) {
        float2 v = row[4 * nc + t];
        int c = 8 * nc + 2 * t;
        float a = v.x * Ss[c];
        float b = v.y * Ss[c + 1];
        if (t == 3 && nc == 7) { a = 0.f; b = 0.f; }   // BOS/EOS cols 62,63
        u[nc] = pack_bf2(a, b);
    }
    uint4* dst = reinterpret_cast<uint4*>(g_Tb) + (size_t)w * 8 + t * 2;
    dst[0] = make_uint4(u[0], u[1], u[2], u[3]);
    dst[1] = make_uint4(u[4], u[5], u[6], u[7]);
}

// ---------------------------------------------------------------------------
// Kernel 5: mma.sync forward recursion (R9 design: 16 sentences/warp,
// register-only). MMA issue restructured: kc-outer/nc-inner with TWO
// accumulator sets (ca: kc0-1, cb: kc2-3) to halve the HMMA dependency chain.
// ---------------------------------------------------------------------------
__global__ void __launch_bounds__(64) forward_mma_kernel(const int* __restrict__ words,
                                                         float* __restrict__ out) {
    int tid  = threadIdx.x;
    int warp = tid >> 5;
    int lane = tid & 31;
    int g = lane >> 2;        // row group: owns rows g, g+8
    int t = lane & 3;         // col/k group

    int base = (blockIdx.x * 2 + warp) * 16;

    // B fragments of A_hmm (col-major): Bf[nc][kc][2]
    uint32_t Bf[8][4][2];
    #pragma unroll
    for (int nc = 0; nc < 8; nc++) {
        int n = 8 * nc + g;
        #pragma unroll
        for (int kc = 0; kc < 4; kc++) {
            int k0 = 16 * kc + 2 * t;
            Bf[nc][kc][0] = pack_bf2(g_A[(k0 + 0) * KT + n], g_A[(k0 + 1) * KT + n]);
            Bf[nc][kc][1] = pack_bf2(g_A[(k0 + 8) * KT + n], g_A[(k0 + 9) * KT + n]);
        }
    }

    // alpha fragments: one-hot at k=62
    uint32_t af[4][4];
    #pragma unroll
    for (int kc = 0; kc < 4; kc++)
        #pragma unroll
        for (int i = 0; i < 4; i++) af[kc][i] = 0u;
    if (t == 3) {
        af[3][2] = 0x00003F80u;
        af[3][3] = 0x00003F80u;
    }

    const int* wpg = words + (size_t)(base + g) * LL;
    const int* wph = words + (size_t)(base + g + 8) * LL;

    const uint4* Tb4 = reinterpret_cast<const uint4*>(g_Tb);

    uint32_t eg[8], eh[8];
    {
        int wg = wpg[0], wh = wph[0];
        uint4 ga = Tb4[(size_t)wg * 8 + t * 2], gb = Tb4[(size_t)wg * 8 + t * 2 + 1];
        uint4 ha = Tb4[(size_t)wh * 8 + t * 2], hb = Tb4[(size_t)wh * 8 + t * 2 + 1];
        eg[0] = ga.x; eg[1] = ga.y; eg[2] = ga.z; eg[3] = ga.w;
        eg[4] = gb.x; eg[5] = gb.y; eg[6] = gb.z; eg[7] = gb.w;
        eh[0] = ha.x; eh[1] = ha.y; eh[2] = ha.z; eh[3] = ha.w;
        eh[4] = hb.x; eh[5] = hb.y; eh[6] = hb.z; eh[7] = hb.w;
    }
    int wg1 = wpg[1], wh1 = wph[1];

    float lsc0 = 0.f, lsc1 = 0.f;

    for (int step = 0; step < LL; step++) {
        // prefetch next emissions + word after
        uint4 ga = Tb4[(size_t)wg1 * 8 + t * 2], gb = Tb4[(size_t)wg1 * 8 + t * 2 + 1];
        uint4 ha = Tb4[(size_t)wh1 * 8 + t * 2], hb = Tb4[(size_t)wh1 * 8 + t * 2 + 1];
        int nx = (step + 2 < LL) ? step + 2 : 0;
        int wg2 = wpg[nx], wh2 = wph[nx];

        // D = alpha @ A_hmm. Two accumulator sets, kc-outer/nc-inner issue:
        // ca accumulates kc0 then kc1; cb accumulates kc2 then kc3. The two
        // chains are independent and each kc level is 8 independent MMAs.
        float ca[8][4], cb[8][4];
        #pragma unroll
        for (int nc = 0; nc < 8; nc++) {
            ca[nc][0] = 0.f; ca[nc][1] = 0.f; ca[nc][2] = 0.f; ca[nc][3] = 0.f;
            cb[nc][0] = 0.f; cb[nc][1] = 0.f; cb[nc][2] = 0.f; cb[nc][3] = 0.f;
        }
        #pragma unroll
        for (int nc = 0; nc < 8; nc++) mma16816(ca[nc], af[0], Bf[nc][0]);
        #pragma unroll
        for (int nc = 0; nc < 8; nc++) mma16816(cb[nc], af[2], Bf[nc][2]);
        #pragma unroll
        for (int nc = 0; nc < 8; nc++) mma16816(ca[nc], af[1], Bf[nc][1]);
        #pragma unroll
        for (int nc = 0; nc < 8; nc++) mma16816(cb[nc], af[3], Bf[nc][3]);

        uint32_t og[8], oh[8];
        if ((step & 15) == 15) {
            // rescale path: merge, f32 emission multiply, per-row max, normalize
            float p[8][4];
            float m0 = -1.f, m1 = -1.f;
            #pragma unroll
            for (int nc = 0; nc < 8; nc++) {
                p[nc][0] = (ca[nc][0] + cb[nc][0]) * blo(eg[nc]);
                p[nc][1] = (ca[nc][1] + cb[nc][1]) * bhi(eg[nc]);
                p[nc][2] = (ca[nc][2] + cb[nc][2]) * blo(eh[nc]);
                p[nc][3] = (ca[nc][3] + cb[nc][3]) * bhi(eh[nc]);
                m0 = fmaxf(m0, fmaxf(p[nc][0], p[nc][1]));
                m1 = fmaxf(m1, fmaxf(p[nc][2], p[nc][3]));
            }
            m0 = fmaxf(m0, __shfl_xor_sync(0xffffffffu, m0, 1));
            m0 = fmaxf(m0, __shfl_xor_sync(0xffffffffu, m0, 2));
            m1 = fmaxf(m1, __shfl_xor_sync(0xffffffffu, m1, 1));
            m1 = fmaxf(m1, __shfl_xor_sync(0xffffffffu, m1, 2));
            float r0 = __fdividef(1.0f, m0);
            float r1 = __fdividef(1.0f, m1);
            lsc0 += __logf(m0);
            lsc1 += __logf(m1);
            #pragma unroll
            for (int nc = 0; nc < 8; nc++) {
                og[nc] = pack_bf2(p[nc][0] * r0, p[nc][1] * r0);
                oh[nc] = pack_bf2(p[nc][2] * r1, p[nc][3] * r1);
            }
        } else {
            // fast path: merge + cvt + packed bf16 multiply -> next fragment
            #pragma unroll
            for (int nc = 0; nc < 8; nc++) {
                og[nc] = mulbf2(pack_bf2(ca[nc][0] + cb[nc][0],
                                         ca[nc][1] + cb[nc][1]), eg[nc]);
                oh[nc] = mulbf2(pack_bf2(ca[nc][2] + cb[nc][2],
                                         ca[nc][3] + cb[nc][3]), eh[nc]);
            }
        }

        // D n-chunk pair -> next A k-chunk fragment
        #pragma unroll
        for (int kc = 0; kc < 4; kc++) {
            af[kc][0] = og[2 * kc];
            af[kc][1] = oh[2 * kc];
            af[kc][2] = og[2 * kc + 1];
            af[kc][3] = oh[2 * kc + 1];
        }

        eg[0] = ga.x; eg[1] = ga.y; eg[2] = ga.z; eg[3] = ga.w;
        eg[4] = gb.x; eg[5] = gb.y; eg[6] = gb.z; eg[7] = gb.w;
        eh[0] = ha.x; eh[1] = ha.y; eh[2] = ha.z; eh[3] = ha.w;
        eh[4] = hb.x; eh[5] = hb.y; eh[6] = hb.z; eh[7] = hb.w;
        wg1 = wg2; wh1 = wh2;
    }

    // final transition into EOS: n-chunk 7 only (col 63 = lane t==3, c1/c3)
    float cz[4] = {0.f, 0.f, 0.f, 0.f};
    #pragma unroll
    for (int kc = 0; kc < 4; kc++)
        mma16816(cz, af[kc], Bf[7][kc]);

    if (t == 3) {
        out[base + g]     = lsc0 + __logf(cz[1]) - CORR_F;
        out[base + g + 8] = lsc1 + __logf(cz[3]) - CORR_F;
    }
}

// ---------------------------------------------------------------------------
// Launch (5 kernels)
// ---------------------------------------------------------------------------
extern "C" void kernel_launch(void* const* d_in, const int* in_sizes, int n_in,
                              void* d_out, int out_size) {
    const int*   words  = nullptr;
    const float* ThetaB = nullptr;
    const float* WA     = nullptr;
    const float* E      = nullptr;
    for (int i = 0; i < n_in; i++) {
        switch (in_sizes[i]) {
            case NB * LL:  words  = (const int*)d_in[i];   break;
            case KT * DD:  ThetaB = (const float*)d_in[i]; break;
            case KT * KT:  WA     = (const float*)d_in[i]; break;
            case VV * DD:  E      = (const float*)d_in[i]; break;
            default: break;
        }
    }
    float* out = (float*)d_out;

    prep_A_kernel<<<1, 64>>>(WA);
    logits_kernel<<<VV / WPB, 256>>>(ThetaB, E);
    zred1_kernel<<<ZBLK, 256>>>();
    bprob_kernel<<<(VV * 4 + 255) / 256, 256>>>();
    forward_mma_kernel<<<NB / 32, 64>>>(words, out);
}